// round 4
// baseline (speedup 1.0000x reference)
#include <cuda_runtime.h>
#include <cuda_bf16.h>
#include <cstdint>

#define NN 8192
#define FF 256

// ---- device scratch ----
__device__ __align__(16) float g_E[NN * FF];             // updated emb (fp32)
__device__ __align__(16) __nv_bfloat16 g_Yt[FF * NN];    // Y^T bf16 [feature][row]
__device__ __align__(16) float g_Gp[8 * FF * FF];        // SYRK split-K partials
__device__ __align__(16) __nv_bfloat16 g_Gh[FF * FF];    // Gram bf16 (symmetric)
__device__ __align__(16) float g_s[2 * FF];              // colsum(Y) per iter
__device__ __align__(16) float g_sf[FF];                 // colsum(final E)
__device__ float g_r[NN];                                // per-row sumsq
__device__ float g_alpha[NN];                            // per-row scale
__device__ float g_Tp1[1024];                            // T partials iter0
__device__ float g_Tp2[128];                             // T partials iter1
__device__ float g_ab[4];                                // a0,b0,a1,b1

// ---- mma / ldmatrix helpers ----
__device__ __forceinline__ uint32_t smem_u32(const void* p) {
    return (uint32_t)__cvta_generic_to_shared(p);
}
__device__ __forceinline__ void ldsm4(uint32_t (&r)[4], uint32_t addr) {
    asm volatile("ldmatrix.sync.aligned.m8n8.x4.shared.b16 {%0,%1,%2,%3}, [%4];"
                 : "=r"(r[0]), "=r"(r[1]), "=r"(r[2]), "=r"(r[3]) : "r"(addr));
}
__device__ __forceinline__ void ldsm4t(uint32_t (&r)[4], uint32_t addr) {
    asm volatile("ldmatrix.sync.aligned.m8n8.x4.trans.shared.b16 {%0,%1,%2,%3}, [%4];"
                 : "=r"(r[0]), "=r"(r[1]), "=r"(r[2]), "=r"(r[3]) : "r"(addr));
}
__device__ __forceinline__ void mma16816(float* c, const uint32_t* a, uint32_t b0, uint32_t b1) {
    asm volatile("mma.sync.aligned.m16n8k16.row.col.f32.bf16.bf16.f32 "
                 "{%0,%1,%2,%3}, {%4,%5,%6,%7}, {%8,%9}, {%0,%1,%2,%3};"
                 : "+f"(c[0]), "+f"(c[1]), "+f"(c[2]), "+f"(c[3])
                 : "r"(a[0]), "r"(a[1]), "r"(a[2]), "r"(a[3]), "r"(b0), "r"(b1));
}

// ---- K0: rownorm partials (blocks 0..1023) + scalars/zeroing (block 1024) ----
__global__ void k_init(const float* __restrict__ X,
                       const float* __restrict__ linear,
                       const float* __restrict__ dirv,
                       const float* __restrict__ feat) {
    int t = threadIdx.x;
    if (blockIdx.x == 1024) {
        // zero accumulators
        g_s[t] = 0.f; g_s[FF + t] = 0.f; g_sf[t] = 0.f;
        // a_i = feat_i . linear_i, b_i = dirv_i . linear_i
        __shared__ float red[256];
        for (int i = 0; i < 2; i++) {
            float pa = feat[i * FF + t] * linear[i * FF + t];
            float pb = dirv[i * FF + t] * linear[i * FF + t];
            red[t] = pa; __syncthreads();
            for (int o = 128; o > 0; o >>= 1) { if (t < o) red[t] += red[t + o]; __syncthreads(); }
            if (t == 0) g_ab[2 * i] = red[0];
            __syncthreads();
            red[t] = pb; __syncthreads();
            for (int o = 128; o > 0; o >>= 1) { if (t < o) red[t] += red[t + o]; __syncthreads(); }
            if (t == 0) g_ab[2 * i + 1] = red[0];
            __syncthreads();
        }
        return;
    }
    int warp = t >> 5, lane = t & 31;
    int row = blockIdx.x * 8 + warp;
    const float* xr = X + row * FF;
    float s = 0.f;
#pragma unroll
    for (int u = 0; u < 8; u++) { float v = xr[lane + 32 * u]; s += v * v; }
#pragma unroll
    for (int o = 16; o > 0; o >>= 1) s += __shfl_xor_sync(0xffffffffu, s, o);
    __shared__ float ws[8];
    if (lane == 0) { ws[warp] = s; g_r[row] = s; }
    __syncthreads();
    if (t == 0) {
        float tt = 0.f;
        for (int w = 0; w < 8; w++) tt += ws[w];
        g_Tp1[blockIdx.x] = tt;
    }
}

// ---- prep: T reduce + alpha inline; Yt[c][j] = bf16(alpha_j*src[j][c]); colsum s ----
__global__ void k_prep(const float* __restrict__ xin, int iter) {
    const float* src = iter ? g_E : xin;
    const float* Tp = iter ? g_Tp2 : g_Tp1;
    int npart = iter ? 128 : 1024;
    __shared__ float red[256];
    __shared__ float sh[64][65];
    __shared__ float csm[64];
    int t = threadIdx.x;
    float tacc = 0.f;
    for (int i = t; i < npart; i += 256) tacc += Tp[i];
    red[t] = tacc; __syncthreads();
    for (int o = 128; o > 0; o >>= 1) { if (t < o) red[t] += red[t + o]; __syncthreads(); }
    float T = red[0];
    __syncthreads();

    float a = g_ab[2 * iter], bb = g_ab[2 * iter + 1];
    float nf = sqrtf(T);
    float sb = (bb >= 0.f) ? 1.f : -1.f;

    int jt = blockIdx.x >> 2;
    int cb = (blockIdx.x & 3) * 64;
    int j0 = jt * 64;
    if (t < 64) csm[t] = 0.f;
    __syncthreads();
    int lr = t >> 4, lc = (t & 15) * 4;
    float ca0 = 0, ca1 = 0, ca2 = 0, ca3 = 0;
#pragma unroll
    for (int w = 0; w < 4; w++) {
        int row = lr + w * 16;
        int J = j0 + row;
        float inner = a * sb * g_r[J] / nf;
        float scale = (inner <= 0.f) ? inner : 0.f;
        float al = a - scale * sb / nf;
        if ((blockIdx.x & 3) == 0 && (t & 15) == 0) g_alpha[J] = al;
        float4 v = *(const float4*)&src[J * FF + cb + lc];
        float y0 = al * v.x, y1 = al * v.y, y2 = al * v.z, y3 = al * v.w;
        sh[row][lc] = y0; sh[row][lc + 1] = y1; sh[row][lc + 2] = y2; sh[row][lc + 3] = y3;
        ca0 += y0; ca1 += y1; ca2 += y2; ca3 += y3;
    }
    atomicAdd(&csm[lc], ca0); atomicAdd(&csm[lc + 1], ca1);
    atomicAdd(&csm[lc + 2], ca2); atomicAdd(&csm[lc + 3], ca3);
    __syncthreads();
    int cl = t >> 4, jl = (t & 15) * 4;
#pragma unroll
    for (int w = 0; w < 4; w++) {
        int c = cl + w * 16;
        __nv_bfloat16 p[4];
        p[0] = __float2bfloat16(sh[jl + 0][c]);
        p[1] = __float2bfloat16(sh[jl + 1][c]);
        p[2] = __float2bfloat16(sh[jl + 2][c]);
        p[3] = __float2bfloat16(sh[jl + 3][c]);
        *(uint2*)&g_Yt[(cb + c) * NN + j0 + jl] = *(uint2*)p;
    }
    if (t < 64) atomicAdd(&g_s[iter * FF + cb + t], csm[t]);
}

// ---- SYRK: Gp[chunk] = partial Y^T Y over 1024 rows (bf16 mma) ----
__global__ __launch_bounds__(256, 2) void k_syrk() {
    __shared__ __nv_bfloat16 Ash[128][72];
    __shared__ __nv_bfloat16 Bsh[128][72];
    int t = threadIdx.x, lane = t & 31, w = t >> 5;
    int wm = w >> 2, wn = w & 3;
    int pa = blockIdx.x >> 1, pb = blockIdx.x & 1;
    int j0 = blockIdx.y * 1024;
    float acc[4][4][4];
#pragma unroll
    for (int i = 0; i < 4; i++)
#pragma unroll
        for (int j = 0; j < 4; j++)
#pragma unroll
            for (int q = 0; q < 4; q++) acc[i][j][q] = 0.f;

    for (int ks = 0; ks < 16; ks++) {
        __syncthreads();
#pragma unroll
        for (int u = 0; u < 4; u++) {
            int idx = t + u * 256;
            int row = idx >> 3, g = idx & 7;
            *(uint4*)&Ash[row][g * 8] = *(const uint4*)&g_Yt[(pa * 128 + row) * NN + j0 + ks * 64 + g * 8];
            *(uint4*)&Bsh[row][g * 8] = *(const uint4*)&g_Yt[(pb * 128 + row) * NN + j0 + ks * 64 + g * 8];
        }
        __syncthreads();
#pragma unroll
        for (int kk = 0; kk < 4; kk++) {
            uint32_t a[4][4], b[2][4];
#pragma unroll
            for (int mi = 0; mi < 4; mi++) {
                int row = wm * 64 + mi * 16 + (lane & 15);
                int col = kk * 16 + 8 * (lane >> 4);
                ldsm4(a[mi], smem_u32(&Ash[row][col]));
            }
#pragma unroll
            for (int p = 0; p < 2; p++) {
                int g = lane >> 3;
                int row = wn * 32 + p * 16 + 8 * (g >> 1) + (lane & 7);
                int col = kk * 16 + 8 * (g & 1);
                ldsm4(b[p], smem_u32(&Bsh[row][col]));
            }
#pragma unroll
            for (int mi = 0; mi < 4; mi++)
#pragma unroll
                for (int nj = 0; nj < 4; nj++)
                    mma16816(acc[mi][nj], a[mi], b[nj >> 1][(nj & 1) * 2], b[nj >> 1][(nj & 1) * 2 + 1]);
        }
    }
    float* gp = &g_Gp[blockIdx.y * (FF * FF)];
#pragma unroll
    for (int mi = 0; mi < 4; mi++)
#pragma unroll
        for (int nj = 0; nj < 4; nj++)
#pragma unroll
            for (int gi = 0; gi < 2; gi++) {
                int row = pa * 128 + wm * 64 + mi * 16 + (lane >> 2) + 8 * gi;
                int col = pb * 128 + wn * 32 + nj * 8 + (lane & 3) * 2;
                *(float2*)&gp[row * FF + col] = make_float2(acc[mi][nj][2 * gi], acc[mi][nj][2 * gi + 1]);
            }
}

// ---- reduce SYRK partials -> Gh bf16 ----
__global__ void k_gred() {
    int i = blockIdx.x * 256 + threadIdx.x;
    float s = 0.f;
#pragma unroll
    for (int ch = 0; ch < 8; ch++) s += g_Gp[ch * (FF * FF) + i];
    g_Gh[i] = __float2bfloat16(s);
}

// ---- update: E = y + (Y.Gh - d*y)/N; fused d, r(E), Tpart, (final) colsum sf ----
__global__ __launch_bounds__(256, 1) void k_update(int iter, const float* __restrict__ xin) {
    const float* src = iter ? g_E : xin;
    __shared__ __nv_bfloat16 Ysh[16][72];
    __shared__ __nv_bfloat16 Gsh[256][24];
    __shared__ float s_sh[FF];
    __shared__ float dsh[64];
    __shared__ float rsm[64];
    __shared__ float csm[FF];
    int t = threadIdx.x, lane = t & 31, w = t >> 5;
    int wm = w >> 2, wn = w & 3;       // 2x4 warps -> 64 rows x 256 cols
    int rowbase = blockIdx.x * 64;
    s_sh[t] = g_s[iter * FF + t];
    csm[t] = 0.f;
    if (t < 64) rsm[t] = 0.f;

    float acc[2][8][4];
#pragma unroll
    for (int i = 0; i < 2; i++)
#pragma unroll
        for (int j = 0; j < 8; j++)
#pragma unroll
            for (int q = 0; q < 4; q++) acc[i][j][q] = 0.f;

    for (int kk = 0; kk < 16; kk++) {
        __syncthreads();
        *(uint2*)&Ysh[t >> 4][(t & 15) * 4] =
            *(const uint2*)&g_Yt[(kk * 16 + (t >> 4)) * NN + rowbase + (t & 15) * 4];
        *(uint4*)&Gsh[t][0] = *(const uint4*)&g_Gh[t * FF + kk * 16];
        *(uint4*)&Gsh[t][8] = *(const uint4*)&g_Gh[t * FF + kk * 16 + 8];
        __syncthreads();
        uint32_t a[2][4], b[4][4];
#pragma unroll
        for (int mi = 0; mi < 2; mi++) {
            int krow = (lane & 7) + 8 * ((lane >> 4) & 1);
            int mcol = wm * 32 + mi * 16 + 8 * ((lane >> 3) & 1);
            ldsm4t(a[mi], smem_u32(&Ysh[krow][mcol]));
        }
#pragma unroll
        for (int p = 0; p < 4; p++) {
            int g = lane >> 3;
            int row = wn * 64 + p * 16 + 8 * (g >> 1) + (lane & 7);
            int col = 8 * (g & 1);
            ldsm4(b[p], smem_u32(&Gsh[row][col]));
        }
#pragma unroll
        for (int mi = 0; mi < 2; mi++)
#pragma unroll
            for (int nj = 0; nj < 8; nj++)
                mma16816(acc[mi][nj], a[mi], b[nj >> 1][(nj & 1) * 2], b[nj >> 1][(nj & 1) * 2 + 1]);
    }

    // per-row d_j = alpha_j * (src_j . s): 8 warps x 8 rows
#pragma unroll
    for (int rr = 0; rr < 8; rr++) {
        int r = w * 8 + rr;
        int Rg = rowbase + r;
        float d = 0.f;
#pragma unroll
        for (int u = 0; u < 8; u++) { int c = lane + 32 * u; d += src[Rg * FF + c] * s_sh[c]; }
#pragma unroll
        for (int o = 16; o > 0; o >>= 1) d += __shfl_xor_sync(0xffffffffu, d, o);
        if (lane == 0) dsh[r] = g_alpha[Rg] * d;
    }
    __syncthreads();

    const float inv = 1.0f / (float)NN;
    float rowsq[2][2] = {{0.f, 0.f}, {0.f, 0.f}};
    float colsm[8][2];
#pragma unroll
    for (int j = 0; j < 8; j++) { colsm[j][0] = 0.f; colsm[j][1] = 0.f; }

#pragma unroll
    for (int mi = 0; mi < 2; mi++)
#pragma unroll
        for (int gi = 0; gi < 2; gi++) {
            int r = wm * 32 + mi * 16 + (lane >> 2) + 8 * gi;
            int Rg = rowbase + r;
            float al = g_alpha[Rg], dd = dsh[r];
#pragma unroll
            for (int nj = 0; nj < 8; nj++) {
                int c = wn * 64 + nj * 8 + (lane & 3) * 2;
                float2 v = *(const float2*)&src[Rg * FF + c];
                float y0 = al * v.x, y1 = al * v.y;
                float e0 = y0 + (acc[mi][nj][2 * gi] - dd * y0) * inv;
                float e1 = y1 + (acc[mi][nj][2 * gi + 1] - dd * y1) * inv;
                *(float2*)&g_E[Rg * FF + c] = make_float2(e0, e1);
                rowsq[mi][gi] += e0 * e0 + e1 * e1;
                colsm[nj][0] += e0; colsm[nj][1] += e1;
            }
        }
#pragma unroll
    for (int mi = 0; mi < 2; mi++)
#pragma unroll
        for (int gi = 0; gi < 2; gi++) {
            float v = rowsq[mi][gi];
            v += __shfl_xor_sync(0xffffffffu, v, 1);
            v += __shfl_xor_sync(0xffffffffu, v, 2);
            if ((lane & 3) == 0)
                atomicAdd(&rsm[wm * 32 + mi * 16 + (lane >> 2) + 8 * gi], v);
        }
    if (iter == 1) {
#pragma unroll
        for (int nj = 0; nj < 8; nj++)
#pragma unroll
            for (int h = 0; h < 2; h++) {
                float v = colsm[nj][h];
                v += __shfl_xor_sync(0xffffffffu, v, 4);
                v += __shfl_xor_sync(0xffffffffu, v, 8);
                v += __shfl_xor_sync(0xffffffffu, v, 16);
                if (lane < 4) atomicAdd(&csm[wn * 64 + nj * 8 + (lane & 3) * 2 + h], v);
            }
    }
    __syncthreads();
    if (t < 64) g_r[rowbase + t] = rsm[t];
    if (t == 0) {
        float tt = 0.f;
        for (int i = 0; i < 64; i++) tt += rsm[i];
        g_Tp2[blockIdx.x] = tt;
    }
    if (iter == 1) atomicAdd(&g_sf[t], csm[t]);
}

// ---- out[j] = E[j] . sf / N ----
__global__ void k_out(float* __restrict__ out) {
    __shared__ float s_sh[FF];
    int t = threadIdx.x;
    s_sh[t] = g_sf[t];
    __syncthreads();
    int warp = t >> 5, lane = t & 31;
    int row = blockIdx.x * 8 + warp;
    if (row >= NN - 1) return;
    float d = 0.f;
#pragma unroll
    for (int u = 0; u < 8; u++) { int c = lane + 32 * u; d += g_E[row * FF + c] * s_sh[c]; }
#pragma unroll
    for (int o = 16; o > 0; o >>= 1) d += __shfl_xor_sync(0xffffffffu, d, o);
    if (lane == 0) out[row] = d * (1.0f / (float)NN);
}

extern "C" void kernel_launch(void* const* d_in, const int* in_sizes, int n_in,
                              void* d_out, int out_size) {
    const float* X      = (const float*)d_in[0];
    const float* linear = (const float*)d_in[2];
    const float* dirv   = (const float*)d_in[3];
    const float* feat   = (const float*)d_in[4];
    float* out = (float*)d_out;

    k_init<<<1025, 256>>>(X, linear, dirv, feat);
    k_prep<<<512, 256>>>(X, 0);
    k_syrk<<<dim3(4, 8), 256>>>();
    k_gred<<<256, 256>>>();
    k_update<<<128, 256>>>(0, X);
    k_prep<<<512, 256>>>(X, 1);
    k_syrk<<<dim3(4, 8), 256>>>();
    k_gred<<<256, 256>>>();
    k_update<<<128, 256>>>(1, X);
    k_out<<<1024, 256>>>(out);
}

// round 5
// speedup vs baseline: 1.5345x; 1.5345x over previous
#include <cuda_runtime.h>
#include <cuda_bf16.h>
#include <cstdint>

#define NN 8192
#define FF 256

// ---- device scratch ----
__device__ __align__(16) float g_E[NN * FF];             // updated emb (fp32)
__device__ __align__(16) __nv_bfloat16 g_Yt[FF * NN];    // Y^T bf16 [feature][row]
__device__ __align__(16) float g_Gp[32 * FF * FF];       // SYRK split-K partials
__device__ __align__(16) __nv_bfloat16 g_Gh[FF * FF];    // Gram bf16 (symmetric)
__device__ __align__(16) float g_s[2 * FF];              // colsum(Y) per iter
__device__ __align__(16) float g_sf[FF];                 // colsum(final E)
__device__ float g_r[NN];                                // per-row sumsq (iter0, from X)
__device__ float g_rp[2 * NN];                           // per-row sumsq partials (iter1)
__device__ float g_alpha[NN];                            // per-row scale
__device__ float g_d[NN];                                // d_j = alpha_j*(src_j.s)
__device__ float g_Tp1[1024];                            // T partials iter0
__device__ float g_Tp2[128];                             // T partials iter1
__device__ float g_ab[4];                                // a0,b0,a1,b1

// ---- mma / ldmatrix helpers ----
__device__ __forceinline__ uint32_t smem_u32(const void* p) {
    return (uint32_t)__cvta_generic_to_shared(p);
}
__device__ __forceinline__ void ldsm4(uint32_t (&r)[4], uint32_t addr) {
    asm volatile("ldmatrix.sync.aligned.m8n8.x4.shared.b16 {%0,%1,%2,%3}, [%4];"
                 : "=r"(r[0]), "=r"(r[1]), "=r"(r[2]), "=r"(r[3]) : "r"(addr));
}
__device__ __forceinline__ void ldsm4t(uint32_t (&r)[4], uint32_t addr) {
    asm volatile("ldmatrix.sync.aligned.m8n8.x4.trans.shared.b16 {%0,%1,%2,%3}, [%4];"
                 : "=r"(r[0]), "=r"(r[1]), "=r"(r[2]), "=r"(r[3]) : "r"(addr));
}
__device__ __forceinline__ void mma16816(float* c, const uint32_t* a, uint32_t b0, uint32_t b1) {
    asm volatile("mma.sync.aligned.m16n8k16.row.col.f32.bf16.bf16.f32 "
                 "{%0,%1,%2,%3}, {%4,%5,%6,%7}, {%8,%9}, {%0,%1,%2,%3};"
                 : "+f"(c[0]), "+f"(c[1]), "+f"(c[2]), "+f"(c[3])
                 : "r"(a[0]), "r"(a[1]), "r"(a[2]), "r"(a[3]), "r"(b0), "r"(b1));
}

// ---- K0: rownorm partials (blocks 0..1023) + scalars/zeroing (block 1024) ----
__global__ void k_init(const float* __restrict__ X,
                       const float* __restrict__ linear,
                       const float* __restrict__ dirv,
                       const float* __restrict__ feat) {
    int t = threadIdx.x;
    if (blockIdx.x == 1024) {
        g_s[t] = 0.f; g_s[FF + t] = 0.f; g_sf[t] = 0.f;
        __shared__ float red[256];
        for (int i = 0; i < 2; i++) {
            float pa = feat[i * FF + t] * linear[i * FF + t];
            float pb = dirv[i * FF + t] * linear[i * FF + t];
            red[t] = pa; __syncthreads();
            for (int o = 128; o > 0; o >>= 1) { if (t < o) red[t] += red[t + o]; __syncthreads(); }
            if (t == 0) g_ab[2 * i] = red[0];
            __syncthreads();
            red[t] = pb; __syncthreads();
            for (int o = 128; o > 0; o >>= 1) { if (t < o) red[t] += red[t + o]; __syncthreads(); }
            if (t == 0) g_ab[2 * i + 1] = red[0];
            __syncthreads();
        }
        return;
    }
    int warp = t >> 5, lane = t & 31;
    int row = blockIdx.x * 8 + warp;
    const float* xr = X + row * FF;
    float s = 0.f;
#pragma unroll
    for (int u = 0; u < 8; u++) { float v = xr[lane + 32 * u]; s += v * v; }
#pragma unroll
    for (int o = 16; o > 0; o >>= 1) s += __shfl_xor_sync(0xffffffffu, s, o);
    __shared__ float ws[8];
    if (lane == 0) { ws[warp] = s; g_r[row] = s; }
    __syncthreads();
    if (t == 0) {
        float tt = 0.f;
        for (int w = 0; w < 8; w++) tt += ws[w];
        g_Tp1[blockIdx.x] = tt;
    }
}

// ---- prep: T reduce + alpha inline; Yt[c][j] = bf16(alpha_j*src[j][c]); colsum s ----
__global__ void k_prep(const float* __restrict__ xin, int iter) {
    const float* src = iter ? g_E : xin;
    const float* Tp = iter ? g_Tp2 : g_Tp1;
    int npart = iter ? 128 : 1024;
    __shared__ float red[256];
    __shared__ float sh[64][65];
    __shared__ float csm[64];
    int t = threadIdx.x;
    float tacc = 0.f;
    for (int i = t; i < npart; i += 256) tacc += Tp[i];
    red[t] = tacc; __syncthreads();
    for (int o = 128; o > 0; o >>= 1) { if (t < o) red[t] += red[t + o]; __syncthreads(); }
    float T = red[0];
    __syncthreads();

    float a = g_ab[2 * iter], bb = g_ab[2 * iter + 1];
    float nf = sqrtf(T);
    float sb = (bb >= 0.f) ? 1.f : -1.f;

    int jt = blockIdx.x >> 2;
    int cb = (blockIdx.x & 3) * 64;
    int j0 = jt * 64;
    if (t < 64) csm[t] = 0.f;
    __syncthreads();
    int lr = t >> 4, lc = (t & 15) * 4;
    float ca0 = 0, ca1 = 0, ca2 = 0, ca3 = 0;
#pragma unroll
    for (int w = 0; w < 4; w++) {
        int row = lr + w * 16;
        int J = j0 + row;
        float rJ = iter ? (g_rp[J] + g_rp[NN + J]) : g_r[J];
        float inner = a * sb * rJ / nf;
        float scale = (inner <= 0.f) ? inner : 0.f;
        float al = a - scale * sb / nf;
        if ((blockIdx.x & 3) == 0 && (t & 15) == 0) g_alpha[J] = al;
        float4 v = *(const float4*)&src[J * FF + cb + lc];
        float y0 = al * v.x, y1 = al * v.y, y2 = al * v.z, y3 = al * v.w;
        sh[row][lc] = y0; sh[row][lc + 1] = y1; sh[row][lc + 2] = y2; sh[row][lc + 3] = y3;
        ca0 += y0; ca1 += y1; ca2 += y2; ca3 += y3;
    }
    atomicAdd(&csm[lc], ca0); atomicAdd(&csm[lc + 1], ca1);
    atomicAdd(&csm[lc + 2], ca2); atomicAdd(&csm[lc + 3], ca3);
    __syncthreads();
    int cl = t >> 4, jl = (t & 15) * 4;
#pragma unroll
    for (int w = 0; w < 4; w++) {
        int c = cl + w * 16;
        __nv_bfloat16 p[4];
        p[0] = __float2bfloat16(sh[jl + 0][c]);
        p[1] = __float2bfloat16(sh[jl + 1][c]);
        p[2] = __float2bfloat16(sh[jl + 2][c]);
        p[3] = __float2bfloat16(sh[jl + 3][c]);
        *(uint2*)&g_Yt[(cb + c) * NN + j0 + jl] = *(uint2*)p;
    }
    if (t < 64) atomicAdd(&g_s[iter * FF + cb + t], csm[t]);
}

// ---- SYRK: Gp[chunk] = partial Y^T Y over 256 rows (bf16 mma); grid (4,32) ----
__global__ __launch_bounds__(256, 2) void k_syrk() {
    __shared__ __nv_bfloat16 Ash[128][72];
    __shared__ __nv_bfloat16 Bsh[128][72];
    int t = threadIdx.x, lane = t & 31, w = t >> 5;
    int wm = w >> 2, wn = w & 3;
    int pa = blockIdx.x >> 1, pb = blockIdx.x & 1;
    int j0 = blockIdx.y * 256;
    float acc[4][4][4];
#pragma unroll
    for (int i = 0; i < 4; i++)
#pragma unroll
        for (int j = 0; j < 4; j++)
#pragma unroll
            for (int q = 0; q < 4; q++) acc[i][j][q] = 0.f;

    for (int ks = 0; ks < 4; ks++) {
        __syncthreads();
#pragma unroll
        for (int u = 0; u < 4; u++) {
            int idx = t + u * 256;
            int row = idx >> 3, g = idx & 7;
            *(uint4*)&Ash[row][g * 8] = *(const uint4*)&g_Yt[(pa * 128 + row) * NN + j0 + ks * 64 + g * 8];
            *(uint4*)&Bsh[row][g * 8] = *(const uint4*)&g_Yt[(pb * 128 + row) * NN + j0 + ks * 64 + g * 8];
        }
        __syncthreads();
#pragma unroll
        for (int kk = 0; kk < 4; kk++) {
            uint32_t a[4][4], b[2][4];
#pragma unroll
            for (int mi = 0; mi < 4; mi++) {
                int row = wm * 64 + mi * 16 + (lane & 15);
                int col = kk * 16 + 8 * (lane >> 4);
                ldsm4(a[mi], smem_u32(&Ash[row][col]));
            }
#pragma unroll
            for (int p = 0; p < 2; p++) {
                int g = lane >> 3;
                int row = wn * 32 + p * 16 + 8 * (g >> 1) + (lane & 7);
                int col = kk * 16 + 8 * (g & 1);
                ldsm4(b[p], smem_u32(&Bsh[row][col]));
            }
#pragma unroll
            for (int mi = 0; mi < 4; mi++)
#pragma unroll
                for (int nj = 0; nj < 4; nj++)
                    mma16816(acc[mi][nj], a[mi], b[nj >> 1][(nj & 1) * 2], b[nj >> 1][(nj & 1) * 2 + 1]);
        }
    }
    float* gp = &g_Gp[blockIdx.y * (FF * FF)];
#pragma unroll
    for (int mi = 0; mi < 4; mi++)
#pragma unroll
        for (int nj = 0; nj < 4; nj++)
#pragma unroll
            for (int gi = 0; gi < 2; gi++) {
                int row = pa * 128 + wm * 64 + mi * 16 + (lane >> 2) + 8 * gi;
                int col = pb * 128 + wn * 32 + nj * 8 + (lane & 3) * 2;
                *(float2*)&gp[row * FF + col] = make_float2(acc[mi][nj][2 * gi], acc[mi][nj][2 * gi + 1]);
            }
}

// ---- reduce SYRK partials -> Gh bf16, AND d[j] = alpha_j*(src_j . s) ----
__global__ void k_gred_dots(const float* __restrict__ xin, int iter) {
    const float* src = iter ? g_E : xin;
    __shared__ float s_sh[FF];
    int t = threadIdx.x;
    s_sh[t] = g_s[iter * FF + t];

    int i = blockIdx.x * 256 + t;
    float sum = 0.f;
#pragma unroll
    for (int ch = 0; ch < 32; ch++) sum += g_Gp[ch * (FF * FF) + i];
    g_Gh[i] = __float2bfloat16(sum);
    __syncthreads();

    int w = t >> 5, lane = t & 31;
#pragma unroll
    for (int rr = 0; rr < 4; rr++) {
        int row = blockIdx.x * 32 + w * 4 + rr;
        const float* r = &src[row * FF];
        float d = 0.f;
#pragma unroll
        for (int u = 0; u < 8; u++) { int c = lane + 32 * u; d += r[c] * s_sh[c]; }
#pragma unroll
        for (int o = 16; o > 0; o >>= 1) d += __shfl_xor_sync(0xffffffffu, d, o);
        if (lane == 0) g_d[row] = g_alpha[row] * d;
    }
}

// ---- update: E = y + (Y.Gh - d*y)/N; r partials, T partials, (iter1) colsum sf ----
__global__ __launch_bounds__(256, 2) void k_update(int iter, const float* __restrict__ xin) {
    const float* src = iter ? g_E : xin;
    __shared__ __nv_bfloat16 Ysh[16][136];
    __shared__ __nv_bfloat16 Gsh[128][24];
    __shared__ float rsm[128];
    __shared__ float csm[128];
    int t = threadIdx.x, lane = t & 31, w = t >> 5;
    int wm = w >> 2, wn = w & 3;
    int rt = blockIdx.x >> 1, ct = blockIdx.x & 1;
    int rowbase = rt * 128, colbase = ct * 128;
    if (t < 128) { rsm[t] = 0.f; csm[t] = 0.f; }
    float acc[4][4][4];
#pragma unroll
    for (int i = 0; i < 4; i++)
#pragma unroll
        for (int j = 0; j < 4; j++)
#pragma unroll
            for (int q = 0; q < 4; q++) acc[i][j][q] = 0.f;

    for (int kk = 0; kk < 16; kk++) {
        __syncthreads();
        {
            int row = t >> 4, g = t & 15;
            *(uint4*)&Ysh[row][g * 8] = *(const uint4*)&g_Yt[(kk * 16 + row) * NN + rowbase + g * 8];
        }
        {
            int n = t >> 1, g = t & 1;
            *(uint4*)&Gsh[n][g * 8] = *(const uint4*)&g_Gh[(colbase + n) * FF + kk * 16 + g * 8];
        }
        __syncthreads();
        uint32_t a[4][4], b[2][4];
#pragma unroll
        for (int mi = 0; mi < 4; mi++) {
            int krow = (lane & 7) + 8 * ((lane >> 4) & 1);
            int mcol = wm * 64 + mi * 16 + 8 * ((lane >> 3) & 1);
            ldsm4t(a[mi], smem_u32(&Ysh[krow][mcol]));
        }
#pragma unroll
        for (int p = 0; p < 2; p++) {
            int g = lane >> 3;
            int row = wn * 32 + p * 16 + 8 * (g >> 1) + (lane & 7);
            int col = 8 * (g & 1);
            ldsm4(b[p], smem_u32(&Gsh[row][col]));
        }
#pragma unroll
        for (int mi = 0; mi < 4; mi++)
#pragma unroll
            for (int nj = 0; nj < 4; nj++)
                mma16816(acc[mi][nj], a[mi], b[nj >> 1][(nj & 1) * 2], b[nj >> 1][(nj & 1) * 2 + 1]);
    }

    const float inv = 1.0f / (float)NN;
    float rowsq[4][2];
    float colsm[4][2];
#pragma unroll
    for (int i = 0; i < 4; i++) { rowsq[i][0] = 0.f; rowsq[i][1] = 0.f; colsm[i][0] = 0.f; colsm[i][1] = 0.f; }

#pragma unroll
    for (int mi = 0; mi < 4; mi++)
#pragma unroll
        for (int gi = 0; gi < 2; gi++) {
            int r = wm * 64 + mi * 16 + (lane >> 2) + 8 * gi;
            int Rg = rowbase + r;
            float al = g_alpha[Rg], dd = g_d[Rg];
#pragma unroll
            for (int nj = 0; nj < 4; nj++) {
                int c = colbase + wn * 32 + nj * 8 + (lane & 3) * 2;
                float2 v = *(const float2*)&src[Rg * FF + c];
                float y0 = al * v.x, y1 = al * v.y;
                float e0 = y0 + (acc[mi][nj][2 * gi] - dd * y0) * inv;
                float e1 = y1 + (acc[mi][nj][2 * gi + 1] - dd * y1) * inv;
                *(float2*)&g_E[Rg * FF + c] = make_float2(e0, e1);
                rowsq[mi][gi] += e0 * e0 + e1 * e1;
                colsm[nj][0] += e0; colsm[nj][1] += e1;
            }
        }
#pragma unroll
    for (int mi = 0; mi < 4; mi++)
#pragma unroll
        for (int gi = 0; gi < 2; gi++) {
            float v = rowsq[mi][gi];
            v += __shfl_xor_sync(0xffffffffu, v, 1);
            v += __shfl_xor_sync(0xffffffffu, v, 2);
            if ((lane & 3) == 0) atomicAdd(&rsm[wm * 64 + mi * 16 + (lane >> 2) + 8 * gi], v);
        }
    if (iter == 1) {
#pragma unroll
        for (int nj = 0; nj < 4; nj++)
#pragma unroll
            for (int h = 0; h < 2; h++) {
                float v = colsm[nj][h];
                v += __shfl_xor_sync(0xffffffffu, v, 4);
                v += __shfl_xor_sync(0xffffffffu, v, 8);
                v += __shfl_xor_sync(0xffffffffu, v, 16);
                if (lane < 4) atomicAdd(&csm[wn * 32 + nj * 8 + (lane & 3) * 2 + h], v);
            }
    }
    __syncthreads();
    if (t < 128) g_rp[ct * NN + rowbase + t] = rsm[t];
    if (t == 0) {
        float tt = 0.f;
        for (int i = 0; i < 128; i++) tt += rsm[i];
        g_Tp2[blockIdx.x] = tt;
    }
    if (iter == 1 && t < 128) atomicAdd(&g_sf[colbase + t], csm[t]);
}

// ---- out[j] = E[j] . sf / N ----
__global__ void k_out(float* __restrict__ out) {
    __shared__ float s_sh[FF];
    int t = threadIdx.x;
    s_sh[t] = g_sf[t];
    __syncthreads();
    int warp = t >> 5, lane = t & 31;
    int row = blockIdx.x * 8 + warp;
    if (row >= NN - 1) return;
    float d = 0.f;
#pragma unroll
    for (int u = 0; u < 8; u++) { int c = lane + 32 * u; d += g_E[row * FF + c] * s_sh[c]; }
#pragma unroll
    for (int o = 16; o > 0; o >>= 1) d += __shfl_xor_sync(0xffffffffu, d, o);
    if (lane == 0) out[row] = d * (1.0f / (float)NN);
}

extern "C" void kernel_launch(void* const* d_in, const int* in_sizes, int n_in,
                              void* d_out, int out_size) {
    const float* X      = (const float*)d_in[0];
    const float* linear = (const float*)d_in[2];
    const float* dirv   = (const float*)d_in[3];
    const float* feat   = (const float*)d_in[4];
    float* out = (float*)d_out;

    k_init<<<1025, 256>>>(X, linear, dirv, feat);
    k_prep<<<512, 256>>>(X, 0);
    k_syrk<<<dim3(4, 32), 256>>>();
    k_gred_dots<<<256, 256>>>(X, 0);
    k_update<<<128, 256>>>(0, X);
    k_prep<<<512, 256>>>(X, 1);
    k_syrk<<<dim3(4, 32), 256>>>();
    k_gred_dots<<<256, 256>>>(X, 1);
    k_update<<<128, 256>>>(1, X);
    k_out<<<1024, 256>>>(out);
}

// round 6
// speedup vs baseline: 1.5699x; 1.0231x over previous
#include <cuda_runtime.h>
#include <cuda_bf16.h>
#include <cstdint>

#define NN 8192
#define FF 256

// ---- device scratch ----
__device__ __align__(16) float g_E[NN * FF];             // updated emb (fp32)
__device__ __align__(16) __nv_bfloat16 g_Yt[FF * NN];    // Y^T bf16 [feature][row]
__device__ __align__(16) float g_Gp[32 * FF * FF];       // SYRK split-K partials
__device__ __align__(16) __nv_bfloat16 g_Gh[FF * FF];    // Gram bf16 (symmetric)
__device__ __align__(16) float g_s[2 * FF];              // colsum(Y) per iter
__device__ __align__(16) float g_sf[FF];                 // colsum(final E)
__device__ float g_r[NN];                                // per-row sumsq (iter0, from X)
__device__ float g_rp[2 * NN];                           // per-row sumsq partials (iter1)
__device__ float g_alpha[NN];                            // per-row scale
__device__ float g_d[NN];                                // d_j = alpha_j*(src_j.s)
__device__ float g_Tp1[1024];                            // T partials iter0
__device__ float g_Tp2[128];                             // T partials iter1
__device__ float g_ab[4];                                // a0,b0,a1,b1

// ---- mma / ldmatrix helpers ----
__device__ __forceinline__ uint32_t smem_u32(const void* p) {
    return (uint32_t)__cvta_generic_to_shared(p);
}
__device__ __forceinline__ void ldsm4(uint32_t (&r)[4], uint32_t addr) {
    asm volatile("ldmatrix.sync.aligned.m8n8.x4.shared.b16 {%0,%1,%2,%3}, [%4];"
                 : "=r"(r[0]), "=r"(r[1]), "=r"(r[2]), "=r"(r[3]) : "r"(addr));
}
__device__ __forceinline__ void ldsm4t(uint32_t (&r)[4], uint32_t addr) {
    asm volatile("ldmatrix.sync.aligned.m8n8.x4.trans.shared.b16 {%0,%1,%2,%3}, [%4];"
                 : "=r"(r[0]), "=r"(r[1]), "=r"(r[2]), "=r"(r[3]) : "r"(addr));
}
__device__ __forceinline__ void mma16816(float* c, const uint32_t* a, uint32_t b0, uint32_t b1) {
    asm volatile("mma.sync.aligned.m16n8k16.row.col.f32.bf16.bf16.f32 "
                 "{%0,%1,%2,%3}, {%4,%5,%6,%7}, {%8,%9}, {%0,%1,%2,%3};"
                 : "+f"(c[0]), "+f"(c[1]), "+f"(c[2]), "+f"(c[3])
                 : "r"(a[0]), "r"(a[1]), "r"(a[2]), "r"(a[3]), "r"(b0), "r"(b1));
}

// ---- K0: rownorm partials (blocks 0..1023) + scalars/zeroing (block 1024) ----
__global__ void k_init(const float* __restrict__ X,
                       const float* __restrict__ linear,
                       const float* __restrict__ dirv,
                       const float* __restrict__ feat) {
    int t = threadIdx.x;
    if (blockIdx.x == 1024) {
        g_s[t] = 0.f; g_s[FF + t] = 0.f; g_sf[t] = 0.f;
        __shared__ float red[256];
        for (int i = 0; i < 2; i++) {
            float pa = feat[i * FF + t] * linear[i * FF + t];
            float pb = dirv[i * FF + t] * linear[i * FF + t];
            red[t] = pa; __syncthreads();
            for (int o = 128; o > 0; o >>= 1) { if (t < o) red[t] += red[t + o]; __syncthreads(); }
            if (t == 0) g_ab[2 * i] = red[0];
            __syncthreads();
            red[t] = pb; __syncthreads();
            for (int o = 128; o > 0; o >>= 1) { if (t < o) red[t] += red[t + o]; __syncthreads(); }
            if (t == 0) g_ab[2 * i + 1] = red[0];
            __syncthreads();
        }
        return;
    }
    int warp = t >> 5, lane = t & 31;
    int row = blockIdx.x * 8 + warp;
    const float* xr = X + row * FF;
    float s = 0.f;
#pragma unroll
    for (int u = 0; u < 8; u++) { float v = xr[lane + 32 * u]; s += v * v; }
#pragma unroll
    for (int o = 16; o > 0; o >>= 1) s += __shfl_xor_sync(0xffffffffu, s, o);
    __shared__ float ws[8];
    if (lane == 0) { ws[warp] = s; g_r[row] = s; }
    __syncthreads();
    if (t == 0) {
        float tt = 0.f;
        for (int w = 0; w < 8; w++) tt += ws[w];
        g_Tp1[blockIdx.x] = tt;
    }
}

// ---- prep: T reduce + alpha inline; Yt[c][j] = bf16(alpha_j*src[j][c]); colsum s ----
__global__ void k_prep(const float* __restrict__ xin, int iter) {
    const float* src = iter ? g_E : xin;
    const float* Tp = iter ? g_Tp2 : g_Tp1;
    int npart = iter ? 128 : 1024;
    __shared__ float red[256];
    __shared__ float sh[64][65];
    __shared__ float csm[64];
    int t = threadIdx.x;
    float tacc = 0.f;
    for (int i = t; i < npart; i += 256) tacc += Tp[i];
    red[t] = tacc; __syncthreads();
    for (int o = 128; o > 0; o >>= 1) { if (t < o) red[t] += red[t + o]; __syncthreads(); }
    float T = red[0];
    __syncthreads();

    float a = g_ab[2 * iter], bb = g_ab[2 * iter + 1];
    float nf = sqrtf(T);
    float sb = (bb >= 0.f) ? 1.f : -1.f;

    int jt = blockIdx.x >> 2;
    int cb = (blockIdx.x & 3) * 64;
    int j0 = jt * 64;
    if (t < 64) csm[t] = 0.f;
    __syncthreads();
    int lr = t >> 4, lc = (t & 15) * 4;
    float ca0 = 0, ca1 = 0, ca2 = 0, ca3 = 0;
#pragma unroll
    for (int w = 0; w < 4; w++) {
        int row = lr + w * 16;
        int J = j0 + row;
        float rJ = iter ? (g_rp[J] + g_rp[NN + J]) : g_r[J];
        float inner = a * sb * rJ / nf;
        float scale = (inner <= 0.f) ? inner : 0.f;
        float al = a - scale * sb / nf;
        if ((blockIdx.x & 3) == 0 && (t & 15) == 0) g_alpha[J] = al;
        float4 v = *(const float4*)&src[J * FF + cb + lc];
        float y0 = al * v.x, y1 = al * v.y, y2 = al * v.z, y3 = al * v.w;
        sh[row][lc] = y0; sh[row][lc + 1] = y1; sh[row][lc + 2] = y2; sh[row][lc + 3] = y3;
        ca0 += y0; ca1 += y1; ca2 += y2; ca3 += y3;
    }
    atomicAdd(&csm[lc], ca0); atomicAdd(&csm[lc + 1], ca1);
    atomicAdd(&csm[lc + 2], ca2); atomicAdd(&csm[lc + 3], ca3);
    __syncthreads();
    int cl = t >> 4, jl = (t & 15) * 4;
#pragma unroll
    for (int w = 0; w < 4; w++) {
        int c = cl + w * 16;
        __nv_bfloat16 p[4];
        p[0] = __float2bfloat16(sh[jl + 0][c]);
        p[1] = __float2bfloat16(sh[jl + 1][c]);
        p[2] = __float2bfloat16(sh[jl + 2][c]);
        p[3] = __float2bfloat16(sh[jl + 3][c]);
        *(uint2*)&g_Yt[(cb + c) * NN + j0 + jl] = *(uint2*)p;
    }
    if (t < 64) atomicAdd(&g_s[iter * FF + cb + t], csm[t]);
}

// ---- SYRK: Gp[chunk] = partial Y^T Y over 256 rows (bf16 mma); grid (4,32) ----
__global__ __launch_bounds__(256, 2) void k_syrk() {
    __shared__ __nv_bfloat16 Ash[128][72];
    __shared__ __nv_bfloat16 Bsh[128][72];
    int t = threadIdx.x, lane = t & 31, w = t >> 5;
    int wm = w >> 2, wn = w & 3;
    int pa = blockIdx.x >> 1, pb = blockIdx.x & 1;
    int j0 = blockIdx.y * 256;
    float acc[4][4][4];
#pragma unroll
    for (int i = 0; i < 4; i++)
#pragma unroll
        for (int j = 0; j < 4; j++)
#pragma unroll
            for (int q = 0; q < 4; q++) acc[i][j][q] = 0.f;

    for (int ks = 0; ks < 4; ks++) {
        __syncthreads();
#pragma unroll
        for (int u = 0; u < 4; u++) {
            int idx = t + u * 256;
            int row = idx >> 3, g = idx & 7;
            *(uint4*)&Ash[row][g * 8] = *(const uint4*)&g_Yt[(pa * 128 + row) * NN + j0 + ks * 64 + g * 8];
            *(uint4*)&Bsh[row][g * 8] = *(const uint4*)&g_Yt[(pb * 128 + row) * NN + j0 + ks * 64 + g * 8];
        }
        __syncthreads();
#pragma unroll
        for (int kk = 0; kk < 4; kk++) {
            uint32_t a[4][4], b[2][4];
#pragma unroll
            for (int mi = 0; mi < 4; mi++) {
                int row = wm * 64 + mi * 16 + (lane & 15);
                int col = kk * 16 + 8 * (lane >> 4);
                ldsm4(a[mi], smem_u32(&Ash[row][col]));
            }
#pragma unroll
            for (int p = 0; p < 2; p++) {
                int g = lane >> 3;
                int row = wn * 32 + p * 16 + 8 * (g >> 1) + (lane & 7);
                int col = kk * 16 + 8 * (g & 1);
                ldsm4(b[p], smem_u32(&Bsh[row][col]));
            }
#pragma unroll
            for (int mi = 0; mi < 4; mi++)
#pragma unroll
                for (int nj = 0; nj < 4; nj++)
                    mma16816(acc[mi][nj], a[mi], b[nj >> 1][(nj & 1) * 2], b[nj >> 1][(nj & 1) * 2 + 1]);
        }
    }
    float* gp = &g_Gp[blockIdx.y * (FF * FF)];
#pragma unroll
    for (int mi = 0; mi < 4; mi++)
#pragma unroll
        for (int nj = 0; nj < 4; nj++)
#pragma unroll
            for (int gi = 0; gi < 2; gi++) {
                int row = pa * 128 + wm * 64 + mi * 16 + (lane >> 2) + 8 * gi;
                int col = pb * 128 + wn * 32 + nj * 8 + (lane & 3) * 2;
                *(float2*)&gp[row * FF + col] = make_float2(acc[mi][nj][2 * gi], acc[mi][nj][2 * gi + 1]);
            }
}

// ---- fused pass, disjoint blocks run concurrently:
//      blocks 0..255   : Gh = bf16(reduce Gp)
//      blocks 256..1279: d[row] = alpha*(src_row . s), 1 row/warp ----
__global__ void k_gred_dots(const float* __restrict__ xin, int iter) {
    int t = threadIdx.x;
    int b = blockIdx.x;
    if (b < 256) {
        int i = b * 256 + t;
        float sum = 0.f;
#pragma unroll
        for (int ch = 0; ch < 32; ch++) sum += g_Gp[ch * (FF * FF) + i];
        g_Gh[i] = __float2bfloat16(sum);
        return;
    }
    const float* src = iter ? g_E : xin;
    __shared__ float s_sh[FF];
    s_sh[t] = g_s[iter * FF + t];
    __syncthreads();
    int w = t >> 5, lane = t & 31;
    int row = (b - 256) * 8 + w;
    const float* r = &src[row * FF];
    float d = 0.f;
#pragma unroll
    for (int u = 0; u < 8; u++) { int c = lane + 32 * u; d += r[c] * s_sh[c]; }
#pragma unroll
    for (int o = 16; o > 0; o >>= 1) d += __shfl_xor_sync(0xffffffffu, d, o);
    if (lane == 0) g_d[row] = g_alpha[row] * d;
}

// ---- update: E = y + (Y.Gh - d*y)/N; r partials, T partials, (iter1) colsum sf ----
__global__ __launch_bounds__(256, 2) void k_update(int iter, const float* __restrict__ xin) {
    const float* src = iter ? g_E : xin;
    __shared__ __nv_bfloat16 Ysh[16][136];
    __shared__ __nv_bfloat16 Gsh[128][24];
    __shared__ float rsm[128];
    __shared__ float csm[128];
    int t = threadIdx.x, lane = t & 31, w = t >> 5;
    int wm = w >> 2, wn = w & 3;
    int rt = blockIdx.x >> 1, ct = blockIdx.x & 1;
    int rowbase = rt * 128, colbase = ct * 128;
    if (t < 128) { rsm[t] = 0.f; csm[t] = 0.f; }
    float acc[4][4][4];
#pragma unroll
    for (int i = 0; i < 4; i++)
#pragma unroll
        for (int j = 0; j < 4; j++)
#pragma unroll
            for (int q = 0; q < 4; q++) acc[i][j][q] = 0.f;

    for (int kk = 0; kk < 16; kk++) {
        __syncthreads();
        {
            int row = t >> 4, g = t & 15;
            *(uint4*)&Ysh[row][g * 8] = *(const uint4*)&g_Yt[(kk * 16 + row) * NN + rowbase + g * 8];
        }
        {
            int n = t >> 1, g = t & 1;
            *(uint4*)&Gsh[n][g * 8] = *(const uint4*)&g_Gh[(colbase + n) * FF + kk * 16 + g * 8];
        }
        __syncthreads();
        uint32_t a[4][4], b[2][4];
#pragma unroll
        for (int mi = 0; mi < 4; mi++) {
            int krow = (lane & 7) + 8 * ((lane >> 4) & 1);
            int mcol = wm * 64 + mi * 16 + 8 * ((lane >> 3) & 1);
            ldsm4t(a[mi], smem_u32(&Ysh[krow][mcol]));
        }
#pragma unroll
        for (int p = 0; p < 2; p++) {
            int g = lane >> 3;
            int row = wn * 32 + p * 16 + 8 * (g >> 1) + (lane & 7);
            int col = 8 * (g & 1);
            ldsm4(b[p], smem_u32(&Gsh[row][col]));
        }
#pragma unroll
        for (int mi = 0; mi < 4; mi++)
#pragma unroll
            for (int nj = 0; nj < 4; nj++)
                mma16816(acc[mi][nj], a[mi], b[nj >> 1][(nj & 1) * 2], b[nj >> 1][(nj & 1) * 2 + 1]);
    }

    const float inv = 1.0f / (float)NN;
    float rowsq[4][2];
    float colsm[4][2];
#pragma unroll
    for (int i = 0; i < 4; i++) { rowsq[i][0] = 0.f; rowsq[i][1] = 0.f; colsm[i][0] = 0.f; colsm[i][1] = 0.f; }

#pragma unroll
    for (int mi = 0; mi < 4; mi++)
#pragma unroll
        for (int gi = 0; gi < 2; gi++) {
            int r = wm * 64 + mi * 16 + (lane >> 2) + 8 * gi;
            int Rg = rowbase + r;
            float al = g_alpha[Rg], dd = g_d[Rg];
#pragma unroll
            for (int nj = 0; nj < 4; nj++) {
                int c = colbase + wn * 32 + nj * 8 + (lane & 3) * 2;
                float2 v = *(const float2*)&src[Rg * FF + c];
                float y0 = al * v.x, y1 = al * v.y;
                float e0 = y0 + (acc[mi][nj][2 * gi] - dd * y0) * inv;
                float e1 = y1 + (acc[mi][nj][2 * gi + 1] - dd * y1) * inv;
                *(float2*)&g_E[Rg * FF + c] = make_float2(e0, e1);
                rowsq[mi][gi] += e0 * e0 + e1 * e1;
                colsm[nj][0] += e0; colsm[nj][1] += e1;
            }
        }
#pragma unroll
    for (int mi = 0; mi < 4; mi++)
#pragma unroll
        for (int gi = 0; gi < 2; gi++) {
            float v = rowsq[mi][gi];
            v += __shfl_xor_sync(0xffffffffu, v, 1);
            v += __shfl_xor_sync(0xffffffffu, v, 2);
            if ((lane & 3) == 0) atomicAdd(&rsm[wm * 64 + mi * 16 + (lane >> 2) + 8 * gi], v);
        }
    if (iter == 1) {
#pragma unroll
        for (int nj = 0; nj < 4; nj++)
#pragma unroll
            for (int h = 0; h < 2; h++) {
                float v = colsm[nj][h];
                v += __shfl_xor_sync(0xffffffffu, v, 4);
                v += __shfl_xor_sync(0xffffffffu, v, 8);
                v += __shfl_xor_sync(0xffffffffu, v, 16);
                if (lane < 4) atomicAdd(&csm[wn * 32 + nj * 8 + (lane & 3) * 2 + h], v);
            }
    }
    __syncthreads();
    if (t < 128) g_rp[ct * NN + rowbase + t] = rsm[t];
    if (t == 0) {
        float tt = 0.f;
        for (int i = 0; i < 128; i++) tt += rsm[i];
        g_Tp2[blockIdx.x] = tt;
    }
    if (iter == 1 && t < 128) atomicAdd(&g_sf[colbase + t], csm[t]);
}

// ---- out[j] = E[j] . sf / N ----
__global__ void k_out(float* __restrict__ out) {
    __shared__ float s_sh[FF];
    int t = threadIdx.x;
    s_sh[t] = g_sf[t];
    __syncthreads();
    int warp = t >> 5, lane = t & 31;
    int row = blockIdx.x * 8 + warp;
    if (row >= NN - 1) return;
    float d = 0.f;
#pragma unroll
    for (int u = 0; u < 8; u++) { int c = lane + 32 * u; d += g_E[row * FF + c] * s_sh[c]; }
#pragma unroll
    for (int o = 16; o > 0; o >>= 1) d += __shfl_xor_sync(0xffffffffu, d, o);
    if (lane == 0) out[row] = d * (1.0f / (float)NN);
}

extern "C" void kernel_launch(void* const* d_in, const int* in_sizes, int n_in,
                              void* d_out, int out_size) {
    const float* X      = (const float*)d_in[0];
    const float* linear = (const float*)d_in[2];
    const float* dirv   = (const float*)d_in[3];
    const float* feat   = (const float*)d_in[4];
    float* out = (float*)d_out;

    k_init<<<1025, 256>>>(X, linear, dirv, feat);
    k_prep<<<512, 256>>>(X, 0);
    k_syrk<<<dim3(4, 32), 256>>>();
    k_gred_dots<<<1280, 256>>>(X, 0);
    k_update<<<128, 256>>>(0, X);
    k_prep<<<512, 256>>>(X, 1);
    k_syrk<<<dim3(4, 32), 256>>>();
    k_gred_dots<<<1280, 256>>>(X, 1);
    k_update<<<128, 256>>>(1, X);
    k_out<<<1024, 256>>>(out);
}